// round 13
// baseline (speedup 1.0000x reference)
#include <cuda_runtime.h>
#include <cuda_fp16.h>
#include <math.h>
#include <stdint.h>

#define BATCH 4
#define NN 4096
#define CC 128
#define QT 64
#define MT 128
#define ITERS (NN / MT)

// f16 scratch, row-major [b*n][c]. Fb is pre-scaled by log2(e).
__device__ __align__(16) __half Fb[BATCH * NN * CC];
__device__ __align__(16) __half Gb[BATCH * NN * CC];
__device__ __align__(16) __half Vb[BATCH * NN * CC];

// ===================== helpers =====================
__device__ __forceinline__ uint32_t smem_u32(const void* p) {
    uint32_t a;
    asm("{ .reg .u64 t; cvta.to.shared.u64 t, %1; cvt.u32.u64 %0, t; }" : "=r"(a) : "l"(p));
    return a;
}
__device__ __forceinline__ uint32_t pack_f16x2(float lo, float hi) {
    uint32_t r;
    asm("cvt.rn.f16x2.f32 %0, %1, %2;" : "=r"(r) : "f"(hi), "f"(lo));
    return r;
}
__device__ __forceinline__ uint32_t ex2_f16x2(uint32_t a) {
    uint32_t r;
    asm("ex2.approx.f16x2 %0, %1;" : "=r"(r) : "r"(a));
    return r;
}
__device__ __forceinline__ uint32_t hadd2u(uint32_t a, uint32_t b) {
    uint32_t r;
    asm("add.f16x2 %0, %1, %2;" : "=r"(r) : "r"(a), "r"(b));
    return r;
}
// blocked SW128 layout for a [128 rows][128 halves] f16 tile (32 KB)
__device__ __forceinline__ uint32_t blk_off(int r, int k) {
    uint32_t byte = ((uint32_t)((r >> 3) + ((k >> 6) << 4)) << 10)
                  + ((uint32_t)(r & 7) << 7) + ((uint32_t)(k & 63) << 1);
    return byte ^ ((byte >> 3) & 0x70);
}
// blocked SW128 layout for a [64 rows][128 halves] f16 tile (16 KB)
__device__ __forceinline__ uint32_t blk_off64(int r, int k) {
    uint32_t byte = ((uint32_t)((r >> 3) + ((k >> 6) << 3)) << 10)
                  + ((uint32_t)(r & 7) << 7) + ((uint32_t)(k & 63) << 1);
    return byte ^ ((byte >> 3) & 0x70);
}
__device__ __forceinline__ void ldsm_x4(uint32_t (&r)[4], uint32_t addr) {
    asm volatile("ldmatrix.sync.aligned.m8n8.x4.shared.b16 {%0,%1,%2,%3}, [%4];"
                 : "=r"(r[0]), "=r"(r[1]), "=r"(r[2]), "=r"(r[3]) : "r"(addr));
}
__device__ __forceinline__ void ldsm_x4_t(uint32_t (&r)[4], uint32_t addr) {
    asm volatile("ldmatrix.sync.aligned.m8n8.x4.trans.shared.b16 {%0,%1,%2,%3}, [%4];"
                 : "=r"(r[0]), "=r"(r[1]), "=r"(r[2]), "=r"(r[3]) : "r"(addr));
}
__device__ __forceinline__ void mma_f32acc(float (&d)[4], uint32_t a0, uint32_t a1,
                                           uint32_t a2, uint32_t a3,
                                           uint32_t b0, uint32_t b1) {
    asm volatile("mma.sync.aligned.m16n8k16.row.col.f32.f16.f16.f32 "
                 "{%0,%1,%2,%3},{%4,%5,%6,%7},{%8,%9},{%0,%1,%2,%3};"
                 : "+f"(d[0]), "+f"(d[1]), "+f"(d[2]), "+f"(d[3])
                 : "r"(a0), "r"(a1), "r"(a2), "r"(a3), "r"(b0), "r"(b1));
}
__device__ __forceinline__ void mma_f16acc2(uint32_t& d0, uint32_t& d1,
                                            uint32_t a0, uint32_t a1,
                                            uint32_t a2, uint32_t a3,
                                            uint32_t b0, uint32_t b1) {
    asm volatile("mma.sync.aligned.m16n8k16.row.col.f16.f16.f16.f16 "
                 "{%0,%1},{%2,%3,%4,%5},{%6,%7},{%0,%1};"
                 : "+r"(d0), "+r"(d1)
                 : "r"(a0), "r"(a1), "r"(a2), "r"(a3), "r"(b0), "r"(b1));
}
__device__ __forceinline__ void cp16(uint32_t d, const void* s) {
    asm volatile("cp.async.cg.shared.global [%0], [%1], 16;" :: "r"(d), "l"(s) : "memory");
}
#define CP_COMMIT() asm volatile("cp.async.commit_group;" ::: "memory")
#define CP_WAIT0()  asm volatile("cp.async.wait_group 0;" ::: "memory")

#define LOG2E 1.4426950408889634f

// ===================== Kernel A: projections via mma.sync (f16 out) =====================
__global__ __launch_bounds__(256, 1)
void proj_kernel(const float* __restrict__ x,
                 const float* __restrict__ Wf, const float* __restrict__ bf,
                 const float* __restrict__ Wg, const float* __restrict__ bg,
                 const float* __restrict__ Wh, const float* __restrict__ bh)
{
    extern __shared__ char smraw[];
    const uint32_t sbase = smem_u32(smraw);
    const uint32_t sal   = (sbase + 1023u) & ~1023u;
    char* smp = smraw + (sal - sbase);
    const uint32_t XT = sal, WT = sal + 32768;

    const int tid  = threadIdx.x;
    const int lane = tid & 31;
    const int wid  = tid >> 5;
    const int wm   = wid & 3;
    const int wn   = wid >> 2;
    const int row0 = blockIdx.x * 128;

    #pragma unroll
    for (int idx = tid; idx < 2048; idx += 256) {
        int r = idx >> 4, kc = idx & 15;
        const float4* s = (const float4*)(x + (size_t)(row0 + r) * CC + kc * 8);
        float4 v0 = s[0], v1 = s[1];
        uint4 pk;
        pk.x = pack_f16x2(v0.x, v0.y); pk.y = pack_f16x2(v0.z, v0.w);
        pk.z = pack_f16x2(v1.x, v1.y); pk.w = pack_f16x2(v1.z, v1.w);
        *(uint4*)(smp + (XT - sal) + blk_off(r, kc * 8)) = pk;
    }

    const float* Ws[3] = {Wf, Wg, Wh};
    const float* bs[3] = {bf, bg, bh};

    for (int w = 0; w < 3; ++w) {
        __syncthreads();
        const float* W = Ws[w];
        #pragma unroll
        for (int idx = tid; idx < 2048; idx += 256) {
            int r = idx >> 4, kc = idx & 15;
            const float4* s = (const float4*)(W + (size_t)r * CC + kc * 8);
            float4 v0 = s[0], v1 = s[1];
            uint4 pk;
            pk.x = pack_f16x2(v0.x, v0.y); pk.y = pack_f16x2(v0.z, v0.w);
            pk.z = pack_f16x2(v1.x, v1.y); pk.w = pack_f16x2(v1.z, v1.w);
            *(uint4*)(smp + (WT - sal) + blk_off(r, kc * 8)) = pk;
        }
        float bc[16];
        #pragma unroll
        for (int t = 0; t < 16; ++t)
            bc[t] = bs[w][64 * wn + 8 * (t >> 1) + 2 * (lane & 3) + (t & 1)];
        __syncthreads();

        float acc[2][8][4];
        #pragma unroll
        for (int i = 0; i < 2; ++i)
            #pragma unroll
            for (int j = 0; j < 8; ++j)
                #pragma unroll
                for (int e = 0; e < 4; ++e) acc[i][j][e] = 0.f;

        #pragma unroll
        for (int ks = 0; ks < 8; ++ks) {
            uint32_t a0[4], a1[4];
            int kcol = 16 * ks + 8 * (lane >> 4);
            ldsm_x4(a0, XT + blk_off(32 * wm + (lane & 15), kcol));
            ldsm_x4(a1, XT + blk_off(32 * wm + 16 + (lane & 15), kcol));
            #pragma unroll
            for (int g = 0; g < 4; ++g) {
                uint32_t bt[4];
                ldsm_x4_t(bt, WT + blk_off(16 * ks + (lane & 15),
                                           64 * wn + 16 * g + 8 * (lane >> 4)));
                mma_f32acc(acc[0][2 * g],     a0[0], a0[1], a0[2], a0[3], bt[0], bt[1]);
                mma_f32acc(acc[0][2 * g + 1], a0[0], a0[1], a0[2], a0[3], bt[2], bt[3]);
                mma_f32acc(acc[1][2 * g],     a1[0], a1[1], a1[2], a1[3], bt[0], bt[1]);
                mma_f32acc(acc[1][2 * g + 1], a1[0], a1[1], a1[2], a1[3], bt[2], bt[3]);
            }
        }

        const float osc = (w == 0) ? LOG2E : 1.0f;   // fold log2e into F
        uint32_t* dst = (uint32_t*)(w == 0 ? Fb : (w == 1 ? Gb : Vb));
        #pragma unroll
        for (int mi = 0; mi < 2; ++mi)
            #pragma unroll
            for (int nj = 0; nj < 8; ++nj) {
                int row  = row0 + 32 * wm + 16 * mi + (lane >> 2);
                int colp = 32 * wn + 4 * nj + (lane & 3);
                float b0 = bc[2 * nj], b1 = bc[2 * nj + 1];
                dst[(size_t)row * 64 + colp] =
                    pack_f16x2((acc[mi][nj][0] + b0) * osc, (acc[mi][nj][1] + b1) * osc);
                dst[(size_t)(row + 8) * 64 + colp] =
                    pack_f16x2((acc[mi][nj][2] + b0) * osc, (acc[mi][nj][3] + b1) * osc);
            }
    }
}

// ===================== Kernel B: 2-CTA/SM desynced flash attention =====================
// grid (64,4) x 128 thr, 2 CTAs/SM. 4 warps = 2 qg x 2 kh; warp = 32q x 64 keys.
// Odd-qtile CTAs rotate the key-tile order by 16 (sum is order-independent).
// smem: F/ctx@0 (16K, 64-row layout), G@16K (32K), V@48K (32K), bvs@80K, lred@+512.
#define SM_F    0
#define SM_G    16384
#define SM_V    49152
#define SM_MISC 81920
#define SM_ATTN (81920 + 1024 + 1024)

__global__ __launch_bounds__(128, 2)
void attn_kernel(const float* __restrict__ x,
                 const float* __restrict__ Wv,
                 const float* __restrict__ bv,
                 const float* __restrict__ gamma_p,
                 float* __restrict__ out)
{
    extern __shared__ char smraw[];
    const uint32_t sbase = smem_u32(smraw);
    const uint32_t sal   = (sbase + 1023u) & ~1023u;
    char* smp = smraw + (sal - sbase);

    const int tid  = threadIdx.x;
    const int lane = tid & 31;
    const int wid  = tid >> 5;
    const int qg   = wid & 1;          // 32-q-row group
    const int kh   = wid >> 1;         // 64-key half
    const int qw   = 32 * qg;
    const int b    = blockIdx.y;
    const int q0   = blockIdx.x * QT;
    const int rot  = (blockIdx.x & 1) * (ITERS / 2);   // de-phase co-resident CTAs

    float* bvs  = (float*)(smp + SM_MISC);
    float* lred = (float*)(smp + SM_MISC + 512);
    bvs[tid] = bv[tid];

    const __half* Gbase = Gb + (size_t)b * NN * CC;
    const __half* Vbase = Vb + (size_t)b * NN * CC;

    // prefetch tile rot (G then V, one group each)
    {
        const __half* gsrc = Gbase + (size_t)rot * MT * CC;
        const __half* vsrc = Vbase + (size_t)rot * MT * CC;
        #pragma unroll
        for (int idx = tid; idx < 2048; idx += 128) {
            int r = idx >> 4, kc = idx & 15;
            uint32_t off = blk_off(r, kc * 8);
            cp16(sal + SM_G + off, gsrc + (size_t)r * CC + kc * 8);
        }
        CP_COMMIT();
        #pragma unroll
        for (int idx = tid; idx < 2048; idx += 128) {
            int r = idx >> 4, kc = idx & 15;
            uint32_t off = blk_off(r, kc * 8);
            cp16(sal + SM_V + off, vsrc + (size_t)r * CC + kc * 8);
        }
        CP_COMMIT();
    }

    // stage F tile (64 x 128, pre-scaled by log2e) in 64-row blocked layout
    #pragma unroll
    for (int idx = tid; idx < 1024; idx += 128) {
        int r = idx >> 4, kc = idx & 15;
        uint4 v = *(const uint4*)(Fb + (size_t)(b * NN + q0 + r) * CC + kc * 8);
        *(uint4*)(smp + SM_F + blk_off64(r, kc * 8)) = v;
    }
    __syncthreads();
    uint32_t aF[2][8][4];
    #pragma unroll
    for (int h = 0; h < 2; ++h)
        #pragma unroll
        for (int ks = 0; ks < 8; ++ks)
            ldsm_x4(aF[h][ks], sal + SM_F + blk_off64(qw + 16 * h + (lane & 15),
                                                      16 * ks + 8 * (lane >> 4)));

    uint32_t ctx[2][16][2];            // f16 accum: 32q x 128c
    #pragma unroll
    for (int h = 0; h < 2; ++h)
        #pragma unroll
        for (int t = 0; t < 16; ++t) { ctx[h][t][0] = 0u; ctx[h][t][1] = 0u; }
    uint32_t lacc[2][2] = {{0u, 0u}, {0u, 0u}};

    const uint32_t GT = sal + SM_G;
    const uint32_t VT = sal + SM_V;

    for (int it = 0; it < ITERS; ++it) {
        CP_WAIT0();
        __syncthreads();               // tile visible; prior epoch fully consumed

        // ---- S = F @ G^T (warp's 64-key half), f16 accum ----
        uint32_t pg[2][8][2];
        #pragma unroll
        for (int h = 0; h < 2; ++h)
            #pragma unroll
            for (int j = 0; j < 8; ++j) { pg[h][j][0] = 0u; pg[h][j][1] = 0u; }

        #pragma unroll
        for (int ks = 0; ks < 8; ++ks) {
            int kcol = 16 * ks + 8 * (lane >> 4);
            #pragma unroll
            for (int g = 0; g < 4; ++g) {
                uint32_t bt[4];
                ldsm_x4(bt, GT + blk_off(64 * kh + 16 * g + (lane & 15), kcol));
                mma_f16acc2(pg[0][2 * g][0],     pg[0][2 * g][1],
                            aF[0][ks][0], aF[0][ks][1], aF[0][ks][2], aF[0][ks][3], bt[0], bt[2]);
                mma_f16acc2(pg[0][2 * g + 1][0], pg[0][2 * g + 1][1],
                            aF[0][ks][0], aF[0][ks][1], aF[0][ks][2], aF[0][ks][3], bt[1], bt[3]);
                mma_f16acc2(pg[1][2 * g][0],     pg[1][2 * g][1],
                            aF[1][ks][0], aF[1][ks][1], aF[1][ks][2], aF[1][ks][3], bt[0], bt[2]);
                mma_f16acc2(pg[1][2 * g + 1][0], pg[1][2 * g + 1][1],
                            aF[1][ks][0], aF[1][ks][1], aF[1][ks][2], aF[1][ks][3], bt[1], bt[3]);
            }
        }
        __syncthreads();               // all warps done reading G

        // issue G(next) — overlaps the PV phase below
        if (it + 1 < ITERS) {
            const __half* gsrc = Gbase + (size_t)(((it + 1 + rot) & (ITERS - 1)) * MT) * CC;
            #pragma unroll
            for (int idx = tid; idx < 2048; idx += 128) {
                int r = idx >> 4, kc = idx & 15;
                cp16(GT + blk_off(r, kc * 8), gsrc + (size_t)r * CC + kc * 8);
            }
            CP_COMMIT();
        }

        // ---- P = 2^S; row sums (ALU); ctx += P @ V ----
        #pragma unroll
        for (int kt = 0; kt < 4; ++kt) {
            const int vrow = 64 * kh + 16 * kt + (lane & 15);
            const int ncol = 8 * (lane >> 4);
            uint32_t vb0[4][4];
            #pragma unroll
            for (int cg = 0; cg < 4; ++cg)
                ldsm_x4_t(vb0[cg], VT + blk_off(vrow, 16 * cg + ncol));

            #pragma unroll
            for (int h = 0; h < 2; ++h) {
                pg[h][2 * kt][0]     = ex2_f16x2(pg[h][2 * kt][0]);
                pg[h][2 * kt][1]     = ex2_f16x2(pg[h][2 * kt][1]);
                pg[h][2 * kt + 1][0] = ex2_f16x2(pg[h][2 * kt + 1][0]);
                pg[h][2 * kt + 1][1] = ex2_f16x2(pg[h][2 * kt + 1][1]);
                lacc[h][0] = hadd2u(lacc[h][0], hadd2u(pg[h][2 * kt][0], pg[h][2 * kt + 1][0]));
                lacc[h][1] = hadd2u(lacc[h][1], hadd2u(pg[h][2 * kt][1], pg[h][2 * kt + 1][1]));
            }

            #pragma unroll
            for (int cg = 0; cg < 4; ++cg)
                #pragma unroll
                for (int h = 0; h < 2; ++h) {
                    mma_f16acc2(ctx[h][2 * cg][0],     ctx[h][2 * cg][1],
                                pg[h][2 * kt][0], pg[h][2 * kt][1],
                                pg[h][2 * kt + 1][0], pg[h][2 * kt + 1][1],
                                vb0[cg][0], vb0[cg][1]);
                    mma_f16acc2(ctx[h][2 * cg + 1][0], ctx[h][2 * cg + 1][1],
                                pg[h][2 * kt][0], pg[h][2 * kt][1],
                                pg[h][2 * kt + 1][0], pg[h][2 * kt + 1][1],
                                vb0[cg][2], vb0[cg][3]);
                }

            uint32_t vb1[4][4];
            #pragma unroll
            for (int cg = 0; cg < 4; ++cg)
                ldsm_x4_t(vb1[cg], VT + blk_off(vrow, 16 * (cg + 4) + ncol));
            #pragma unroll
            for (int cg = 0; cg < 4; ++cg)
                #pragma unroll
                for (int h = 0; h < 2; ++h) {
                    mma_f16acc2(ctx[h][2 * (cg + 4)][0],     ctx[h][2 * (cg + 4)][1],
                                pg[h][2 * kt][0], pg[h][2 * kt][1],
                                pg[h][2 * kt + 1][0], pg[h][2 * kt + 1][1],
                                vb1[cg][0], vb1[cg][1]);
                    mma_f16acc2(ctx[h][2 * (cg + 4) + 1][0], ctx[h][2 * (cg + 4) + 1][1],
                                pg[h][2 * kt][0], pg[h][2 * kt][1],
                                pg[h][2 * kt + 1][0], pg[h][2 * kt + 1][1],
                                vb1[cg][2], vb1[cg][3]);
                }
        }
        __syncthreads();               // all warps done reading V

        // issue V(next)
        if (it + 1 < ITERS) {
            const __half* vsrc = Vbase + (size_t)(((it + 1 + rot) & (ITERS - 1)) * MT) * CC;
            #pragma unroll
            for (int idx = tid; idx < 2048; idx += 128) {
                int r = idx >> 4, kc = idx & 15;
                cp16(VT + blk_off(r, kc * 8), vsrc + (size_t)r * CC + kc * 8);
            }
            CP_COMMIT();
        }
    }

    // ---- l partials ----
    #pragma unroll
    for (int h = 0; h < 2; ++h) {
        float2 v0 = __half22float2(*(__half2*)&lacc[h][0]);
        float2 v1 = __half22float2(*(__half2*)&lacc[h][1]);
        float l0 = v0.x + v0.y;
        float l1 = v1.x + v1.y;
        l0 += __shfl_xor_sync(0xffffffffu, l0, 1);
        l0 += __shfl_xor_sync(0xffffffffu, l0, 2);
        l1 += __shfl_xor_sync(0xffffffffu, l1, 1);
        l1 += __shfl_xor_sync(0xffffffffu, l1, 2);
        if ((lane & 3) == 0) {
            int row = qw + 16 * h + (lane >> 2);
            lred[row * 2 + kh]       = l0;
            lred[(row + 8) * 2 + kh] = l1;
        }
    }

    // ---- phase 1: kh=0 warps store ctx into F region (64-row layout) ----
    if (kh == 0) {
        #pragma unroll
        for (int h = 0; h < 2; ++h)
            #pragma unroll
            for (int t = 0; t < 16; ++t) {
                int row = qw + 16 * h + (lane >> 2);
                int col = 8 * t + 2 * (lane & 3);
                *(uint32_t*)(smp + SM_F + blk_off64(row, col))     = ctx[h][t][0];
                *(uint32_t*)(smp + SM_F + blk_off64(row + 8, col)) = ctx[h][t][1];
            }
    }
    __syncthreads();

    // ---- phase 2: kh=1 adds its ctx; kh=0 warps load Wv tile into G region ----
    if (kh == 1) {
        #pragma unroll
        for (int h = 0; h < 2; ++h)
            #pragma unroll
            for (int t = 0; t < 16; ++t) {
                int row = qw + 16 * h + (lane >> 2);
                int col = 8 * t + 2 * (lane & 3);
                uint32_t* p0 = (uint32_t*)(smp + SM_F + blk_off64(row, col));
                uint32_t* p1 = (uint32_t*)(smp + SM_F + blk_off64(row + 8, col));
                __half2 s0 = __hadd2(*(__half2*)p0, *(__half2*)&ctx[h][t][0]);
                __half2 s1 = __hadd2(*(__half2*)p1, *(__half2*)&ctx[h][t][1]);
                *p0 = *(uint32_t*)&s0;
                *p1 = *(uint32_t*)&s1;
            }
    } else {
        #pragma unroll
        for (int idx = tid; idx < 2048; idx += 64) {   // kh==0: 64 threads
            int r = idx >> 4, kc = idx & 15;
            const float4* s = (const float4*)(Wv + (size_t)r * CC + kc * 8);
            float4 v0 = s[0], v1 = s[1];
            uint4 pk;
            pk.x = pack_f16x2(v0.x, v0.y); pk.y = pack_f16x2(v0.z, v0.w);
            pk.z = pack_f16x2(v1.x, v1.y); pk.w = pack_f16x2(v1.z, v1.w);
            *(uint4*)(smp + SM_G + blk_off(r, kc * 8)) = pk;
        }
    }
    __syncthreads();

    // ---- phase 3: out = (gamma/l) * (ctx @ Wv) + bv + x ; warp = 16q slice ----
    const int qw16 = 16 * wid;
    float oac[16][4];
    #pragma unroll
    for (int t = 0; t < 16; ++t)
        #pragma unroll
        for (int e = 0; e < 4; ++e) oac[t][e] = 0.f;

    #pragma unroll
    for (int ks = 0; ks < 8; ++ks) {
        uint32_t a[4];
        ldsm_x4(a, sal + SM_F + blk_off64(qw16 + (lane & 15), 16 * ks + 8 * (lane >> 4)));
        int ncol = 8 * (lane >> 4);
        #pragma unroll
        for (int g = 0; g < 8; ++g) {
            uint32_t bt[4];
            ldsm_x4_t(bt, sal + SM_G + blk_off(16 * ks + (lane & 15), 16 * g + ncol));
            mma_f32acc(oac[2 * g],     a[0], a[1], a[2], a[3], bt[0], bt[1]);
            mma_f32acc(oac[2 * g + 1], a[0], a[1], a[2], a[3], bt[2], bt[3]);
        }
    }

    const float gamma = __ldg(gamma_p);
    const int r  = lane >> 2;
    const int c2 = 2 * (lane & 3);
    const float sc0 = gamma / (lred[(qw16 + r) * 2]     + lred[(qw16 + r) * 2 + 1]);
    const float sc1 = gamma / (lred[(qw16 + r + 8) * 2] + lred[(qw16 + r + 8) * 2 + 1]);
    #pragma unroll
    for (int t = 0; t < 16; ++t) {
        int j = 8 * t + c2;
        float bj0 = bvs[j], bj1 = bvs[j + 1];
        size_t base0 = (size_t)(b * NN + q0 + qw16 + r) * CC + j;
        size_t base1 = base0 + 8 * CC;
        float2 x0 = *(const float2*)(x + base0);
        float2 x1 = *(const float2*)(x + base1);
        float2 o0, o1;
        o0.x = oac[t][0] * sc0 + bj0 + x0.x;
        o0.y = oac[t][1] * sc0 + bj1 + x0.y;
        o1.x = oac[t][2] * sc1 + bj0 + x1.x;
        o1.y = oac[t][3] * sc1 + bj1 + x1.y;
        *(float2*)(out + base0) = o0;
        *(float2*)(out + base1) = o1;
    }
}

// ===================== launch =====================
extern "C" void kernel_launch(void* const* d_in, const int* in_sizes, int n_in,
                              void* d_out, int out_size)
{
    const float* x     = (const float*)d_in[0];
    const float* Wf    = (const float*)d_in[1];
    const float* bf    = (const float*)d_in[2];
    const float* Wg    = (const float*)d_in[3];
    const float* bg    = (const float*)d_in[4];
    const float* Wh    = (const float*)d_in[5];
    const float* bh    = (const float*)d_in[6];
    const float* Wv    = (const float*)d_in[7];
    const float* bv    = (const float*)d_in[8];
    const float* gamma = (const float*)d_in[9];
    float* out = (float*)d_out;

    const int smem_proj = 2 * 32768 + 1024;
    const int smem_attn = SM_ATTN;

    cudaFuncSetAttribute(proj_kernel, cudaFuncAttributeMaxDynamicSharedMemorySize, smem_proj);
    cudaFuncSetAttribute(attn_kernel, cudaFuncAttributeMaxDynamicSharedMemorySize, smem_attn);

    proj_kernel<<<BATCH * NN / 128, 256, smem_proj>>>(x, Wf, bf, Wg, bg, Wh, bh);

    dim3 grid(NN / QT, BATCH);
    attn_kernel<<<grid, 128, smem_attn>>>(x, Wv, bv, gamma, out);
}

// round 14
// speedup vs baseline: 1.0714x; 1.0714x over previous
#include <cuda_runtime.h>
#include <cuda_fp16.h>
#include <math.h>
#include <stdint.h>

#define BATCH 4
#define NN 4096
#define CC 128
#define QT 128
#define MT 128
#define ITERS (NN / MT)

// f16 scratch, row-major [b*n][c]. Fb is pre-scaled by log2(e).
__device__ __align__(16) __half Fb[BATCH * NN * CC];
__device__ __align__(16) __half Gb[BATCH * NN * CC];
__device__ __align__(16) __half Vb[BATCH * NN * CC];

// ===================== helpers =====================
__device__ __forceinline__ uint32_t smem_u32(const void* p) {
    uint32_t a;
    asm("{ .reg .u64 t; cvta.to.shared.u64 t, %1; cvt.u32.u64 %0, t; }" : "=r"(a) : "l"(p));
    return a;
}
__device__ __forceinline__ uint32_t pack_f16x2(float lo, float hi) {
    uint32_t r;
    asm("cvt.rn.f16x2.f32 %0, %1, %2;" : "=r"(r) : "f"(hi), "f"(lo));
    return r;
}
__device__ __forceinline__ uint32_t ex2_f16x2(uint32_t a) {
    uint32_t r;
    asm("ex2.approx.f16x2 %0, %1;" : "=r"(r) : "r"(a));
    return r;
}
__device__ __forceinline__ uint32_t hadd2u(uint32_t a, uint32_t b) {
    uint32_t r;
    asm("add.f16x2 %0, %1, %2;" : "=r"(r) : "r"(a), "r"(b));
    return r;
}
// blocked SW128 layout for a [128 rows][128 halves] f16 tile (32 KB)
__device__ __forceinline__ uint32_t blk_off(int r, int k) {
    uint32_t byte = ((uint32_t)((r >> 3) + ((k >> 6) << 4)) << 10)
                  + ((uint32_t)(r & 7) << 7) + ((uint32_t)(k & 63) << 1);
    return byte ^ ((byte >> 3) & 0x70);
}
__device__ __forceinline__ void ldsm_x4(uint32_t (&r)[4], uint32_t addr) {
    asm volatile("ldmatrix.sync.aligned.m8n8.x4.shared.b16 {%0,%1,%2,%3}, [%4];"
                 : "=r"(r[0]), "=r"(r[1]), "=r"(r[2]), "=r"(r[3]) : "r"(addr));
}
__device__ __forceinline__ void ldsm_x4_t(uint32_t (&r)[4], uint32_t addr) {
    asm volatile("ldmatrix.sync.aligned.m8n8.x4.trans.shared.b16 {%0,%1,%2,%3}, [%4];"
                 : "=r"(r[0]), "=r"(r[1]), "=r"(r[2]), "=r"(r[3]) : "r"(addr));
}
__device__ __forceinline__ void mma_f32acc(float (&d)[4], uint32_t a0, uint32_t a1,
                                           uint32_t a2, uint32_t a3,
                                           uint32_t b0, uint32_t b1) {
    asm volatile("mma.sync.aligned.m16n8k16.row.col.f32.f16.f16.f32 "
                 "{%0,%1,%2,%3},{%4,%5,%6,%7},{%8,%9},{%0,%1,%2,%3};"
                 : "+f"(d[0]), "+f"(d[1]), "+f"(d[2]), "+f"(d[3])
                 : "r"(a0), "r"(a1), "r"(a2), "r"(a3), "r"(b0), "r"(b1));
}
__device__ __forceinline__ void mma_f16acc2(uint32_t& d0, uint32_t& d1,
                                            uint32_t a0, uint32_t a1,
                                            uint32_t a2, uint32_t a3,
                                            uint32_t b0, uint32_t b1) {
    asm volatile("mma.sync.aligned.m16n8k16.row.col.f16.f16.f16.f16 "
                 "{%0,%1},{%2,%3,%4,%5},{%6,%7},{%0,%1};"
                 : "+r"(d0), "+r"(d1)
                 : "r"(a0), "r"(a1), "r"(a2), "r"(a3), "r"(b0), "r"(b1));
}
__device__ __forceinline__ void cp16(uint32_t d, const void* s) {
    asm volatile("cp.async.cg.shared.global [%0], [%1], 16;" :: "r"(d), "l"(s) : "memory");
}
#define CP_COMMIT() asm volatile("cp.async.commit_group;" ::: "memory")
#define CP_WAIT0()  asm volatile("cp.async.wait_group 0;" ::: "memory")
#define CP_WAIT1()  asm volatile("cp.async.wait_group 1;" ::: "memory")

#define LOG2E 1.4426950408889634f

// ===================== Kernel A: projections, one weight per CTA =====================
// grid (128 tiles, 3 weights) x 256 thr. Each CTA: one 128x128x128 GEMM.
__global__ __launch_bounds__(256, 1)
void proj_kernel(const float* __restrict__ x,
                 const float* __restrict__ Wf, const float* __restrict__ bf,
                 const float* __restrict__ Wg, const float* __restrict__ bg,
                 const float* __restrict__ Wh, const float* __restrict__ bh)
{
    extern __shared__ char smraw[];
    const uint32_t sbase = smem_u32(smraw);
    const uint32_t sal   = (sbase + 1023u) & ~1023u;
    char* smp = smraw + (sal - sbase);
    const uint32_t XT = sal, WT = sal + 32768;

    const int tid  = threadIdx.x;
    const int lane = tid & 31;
    const int wid  = tid >> 5;
    const int wm   = wid & 3;
    const int wn   = wid >> 2;
    const int row0 = blockIdx.x * 128;
    const int w    = blockIdx.y;

    const float* W  = (w == 0) ? Wf : (w == 1 ? Wg : Wh);
    const float* bs = (w == 0) ? bf : (w == 1 ? bg : bh);

    #pragma unroll
    for (int idx = tid; idx < 2048; idx += 256) {
        int r = idx >> 4, kc = idx & 15;
        const float4* s0 = (const float4*)(x + (size_t)(row0 + r) * CC + kc * 8);
        const float4* s1 = (const float4*)(W + (size_t)r * CC + kc * 8);
        float4 v0 = s0[0], v1 = s0[1];
        uint4 pk;
        pk.x = pack_f16x2(v0.x, v0.y); pk.y = pack_f16x2(v0.z, v0.w);
        pk.z = pack_f16x2(v1.x, v1.y); pk.w = pack_f16x2(v1.z, v1.w);
        *(uint4*)(smp + (XT - sal) + blk_off(r, kc * 8)) = pk;
        v0 = s1[0]; v1 = s1[1];
        pk.x = pack_f16x2(v0.x, v0.y); pk.y = pack_f16x2(v0.z, v0.w);
        pk.z = pack_f16x2(v1.x, v1.y); pk.w = pack_f16x2(v1.z, v1.w);
        *(uint4*)(smp + (WT - sal) + blk_off(r, kc * 8)) = pk;
    }
    float bc[16];
    #pragma unroll
    for (int t = 0; t < 16; ++t)
        bc[t] = bs[64 * wn + 8 * (t >> 1) + 2 * (lane & 3) + (t & 1)];
    __syncthreads();

    float acc[2][8][4];
    #pragma unroll
    for (int i = 0; i < 2; ++i)
        #pragma unroll
        for (int j = 0; j < 8; ++j)
            #pragma unroll
            for (int e = 0; e < 4; ++e) acc[i][j][e] = 0.f;

    #pragma unroll
    for (int ks = 0; ks < 8; ++ks) {
        uint32_t a0[4], a1[4];
        int kcol = 16 * ks + 8 * (lane >> 4);
        ldsm_x4(a0, XT + blk_off(32 * wm + (lane & 15), kcol));
        ldsm_x4(a1, XT + blk_off(32 * wm + 16 + (lane & 15), kcol));
        #pragma unroll
        for (int g = 0; g < 4; ++g) {
            uint32_t bt[4];
            ldsm_x4_t(bt, WT + blk_off(16 * ks + (lane & 15),
                                       64 * wn + 16 * g + 8 * (lane >> 4)));
            mma_f32acc(acc[0][2 * g],     a0[0], a0[1], a0[2], a0[3], bt[0], bt[1]);
            mma_f32acc(acc[0][2 * g + 1], a0[0], a0[1], a0[2], a0[3], bt[2], bt[3]);
            mma_f32acc(acc[1][2 * g],     a1[0], a1[1], a1[2], a1[3], bt[0], bt[1]);
            mma_f32acc(acc[1][2 * g + 1], a1[0], a1[1], a1[2], a1[3], bt[2], bt[3]);
        }
    }

    const float osc = (w == 0) ? LOG2E : 1.0f;   // fold log2e into F
    uint32_t* dst = (uint32_t*)(w == 0 ? Fb : (w == 1 ? Gb : Vb));
    #pragma unroll
    for (int mi = 0; mi < 2; ++mi)
        #pragma unroll
        for (int nj = 0; nj < 8; ++nj) {
            int row  = row0 + 32 * wm + 16 * mi + (lane >> 2);
            int colp = 32 * wn + 4 * nj + (lane & 3);
            float b0 = bc[2 * nj], b1 = bc[2 * nj + 1];
            dst[(size_t)row * 64 + colp] =
                pack_f16x2((acc[mi][nj][0] + b0) * osc, (acc[mi][nj][1] + b1) * osc);
            dst[(size_t)(row + 8) * 64 + colp] =
                pack_f16x2((acc[mi][nj][2] + b0) * osc, (acc[mi][nj][3] + b1) * osc);
        }
}

// ===================== Kernel B: 3-stage single-barrier flash attention =====================
// grid (32,4) x 256 thr. 8 warps = 4 qg x 2 kh; warp owns q[32qg,+32) x keys[64kh,+64).
// Depth-1 ldsm double-buffering in S and PV phases (break ldsm->mma RAW exposure).
// smem: B0@0 (G+V 64K), B1@65536, B2@131072 (F staged here first),
//       bvs@196608 (512B), lred@+512 (1KB). Epilogue: ctx->B0, Wv->B1.
#define SM_B0   0
#define SM_B1   65536
#define SM_B2   131072
#define SM_MISC 196608
#define SM_ATTN (196608 + 1536 + 1024)

__global__ __launch_bounds__(256, 1)
void attn_kernel(const float* __restrict__ x,
                 const float* __restrict__ Wv,
                 const float* __restrict__ bv,
                 const float* __restrict__ gamma_p,
                 float* __restrict__ out)
{
    extern __shared__ char smraw[];
    const uint32_t sbase = smem_u32(smraw);
    const uint32_t sal   = (sbase + 1023u) & ~1023u;
    char* smp = smraw + (sal - sbase);

    const int tid  = threadIdx.x;
    const int lane = tid & 31;
    const int wid  = tid >> 5;
    const int qg   = wid & 3;          // 32-q-row group
    const int kh   = wid >> 2;         // 64-key half
    const int qw   = 32 * qg;
    const int b    = blockIdx.y;
    const int q0   = blockIdx.x * QT;

    float* bvs  = (float*)(smp + SM_MISC);
    float* lred = (float*)(smp + SM_MISC + 512);
    if (tid < 128) bvs[tid] = bv[tid];

    const __half* Gbase = Gb + (size_t)b * NN * CC;
    const __half* Vbase = Vb + (size_t)b * NN * CC;

    // prefetch tiles 0 and 1 (separate commit groups)
    #pragma unroll
    for (int idx = tid; idx < 2048; idx += 256) {
        int r = idx >> 4, kc = idx & 15;
        uint32_t off = blk_off(r, kc * 8);
        cp16(sal + SM_B0 + off,         Gbase + (size_t)r * CC + kc * 8);
        cp16(sal + SM_B0 + 32768 + off, Vbase + (size_t)r * CC + kc * 8);
    }
    CP_COMMIT();
    #pragma unroll
    for (int idx = tid; idx < 2048; idx += 256) {
        int r = idx >> 4, kc = idx & 15;
        uint32_t off = blk_off(r, kc * 8);
        cp16(sal + SM_B1 + off,         Gbase + (size_t)(MT + r) * CC + kc * 8);
        cp16(sal + SM_B1 + 32768 + off, Vbase + (size_t)(MT + r) * CC + kc * 8);
    }
    CP_COMMIT();

    // stage F tile (pre-scaled by log2e) into B2; consume into registers
    #pragma unroll
    for (int idx = tid; idx < 2048; idx += 256) {
        int r = idx >> 4, kc = idx & 15;
        uint4 v = *(const uint4*)(Fb + (size_t)(b * NN + q0 + r) * CC + kc * 8);
        *(uint4*)(smp + SM_B2 + blk_off(r, kc * 8)) = v;
    }
    __syncthreads();
    uint32_t aF[2][8][4];
    #pragma unroll
    for (int h = 0; h < 2; ++h)
        #pragma unroll
        for (int ks = 0; ks < 8; ++ks)
            ldsm_x4(aF[h][ks], sal + SM_B2 + blk_off(qw + 16 * h + (lane & 15),
                                                     16 * ks + 8 * (lane >> 4)));

    uint32_t ctx[2][16][2];            // f16 accum: 32q x 128c
    #pragma unroll
    for (int h = 0; h < 2; ++h)
        #pragma unroll
        for (int t = 0; t < 16; ++t) { ctx[h][t][0] = 0u; ctx[h][t][1] = 0u; }
    uint32_t lacc[2][2] = {{0u, 0u}, {0u, 0u}};

    for (int it = 0; it < ITERS; ++it) {
        if (it + 1 < ITERS) { CP_WAIT1(); } else { CP_WAIT0(); }
        __syncthreads();   // publish tile `it`; everyone done with tile it-1

        const uint32_t GT = sal + (uint32_t)((it % 3) * 65536);
        const uint32_t VT = GT + 32768;

        // ---- S = F @ G^T (warp's 64-key half), f16 accum, ldsm depth-1 prefetch ----
        uint32_t pg[2][8][2];
        #pragma unroll
        for (int h = 0; h < 2; ++h)
            #pragma unroll
            for (int j = 0; j < 8; ++j) { pg[h][j][0] = 0u; pg[h][j][1] = 0u; }

        {
            const int klo = 8 * (lane >> 4);
            const int rlo = 64 * kh + (lane & 15);
            uint32_t bt[2][4];
            ldsm_x4(bt[0], GT + blk_off(rlo, klo));          // ks=0, g=0
            #pragma unroll
            for (int ks = 0; ks < 8; ++ks)
                #pragma unroll
                for (int g = 0; g < 4; ++g) {
                    const int cur = (4 * ks + g) & 1;
                    if (!(ks == 7 && g == 3)) {
                        int g2  = (g + 1) & 3;
                        int ks2 = ks + (g == 3);
                        ldsm_x4(bt[cur ^ 1], GT + blk_off(rlo + 16 * g2, 16 * ks2 + klo));
                    }
                    mma_f16acc2(pg[0][2 * g][0],     pg[0][2 * g][1],
                                aF[0][ks][0], aF[0][ks][1], aF[0][ks][2], aF[0][ks][3],
                                bt[cur][0], bt[cur][2]);
                    mma_f16acc2(pg[0][2 * g + 1][0], pg[0][2 * g + 1][1],
                                aF[0][ks][0], aF[0][ks][1], aF[0][ks][2], aF[0][ks][3],
                                bt[cur][1], bt[cur][3]);
                    mma_f16acc2(pg[1][2 * g][0],     pg[1][2 * g][1],
                                aF[1][ks][0], aF[1][ks][1], aF[1][ks][2], aF[1][ks][3],
                                bt[cur][0], bt[cur][2]);
                    mma_f16acc2(pg[1][2 * g + 1][0], pg[1][2 * g + 1][1],
                                aF[1][ks][0], aF[1][ks][1], aF[1][ks][2], aF[1][ks][3],
                                bt[cur][1], bt[cur][3]);
                }
        }

        // ---- per-16-key groups: ex2 + PV with depth-1 V prefetch ----
        #pragma unroll
        for (int kt = 0; kt < 4; ++kt) {
            const int vrow = 64 * kh + 16 * kt + (lane & 15);
            const int ncol = 8 * (lane >> 4);

            // ex2 of this group's P (no V dependency)
            #pragma unroll
            for (int h = 0; h < 2; ++h) {
                pg[h][2 * kt][0]     = ex2_f16x2(pg[h][2 * kt][0]);
                pg[h][2 * kt][1]     = ex2_f16x2(pg[h][2 * kt][1]);
                pg[h][2 * kt + 1][0] = ex2_f16x2(pg[h][2 * kt + 1][0]);
                pg[h][2 * kt + 1][1] = ex2_f16x2(pg[h][2 * kt + 1][1]);
                lacc[h][0] = hadd2u(lacc[h][0], hadd2u(pg[h][2 * kt][0], pg[h][2 * kt + 1][0]));
                lacc[h][1] = hadd2u(lacc[h][1], hadd2u(pg[h][2 * kt][1], pg[h][2 * kt + 1][1]));
            }

            uint32_t vpf[2][4];
            ldsm_x4_t(vpf[0], VT + blk_off(vrow, ncol));      // cg=0
            #pragma unroll
            for (int cg = 0; cg < 8; ++cg) {
                const int cur = cg & 1;
                if (cg < 7)
                    ldsm_x4_t(vpf[cur ^ 1], VT + blk_off(vrow, 16 * (cg + 1) + ncol));
                #pragma unroll
                for (int h = 0; h < 2; ++h) {
                    mma_f16acc2(ctx[h][2 * cg][0],     ctx[h][2 * cg][1],
                                pg[h][2 * kt][0], pg[h][2 * kt][1],
                                pg[h][2 * kt + 1][0], pg[h][2 * kt + 1][1],
                                vpf[cur][0], vpf[cur][1]);
                    mma_f16acc2(ctx[h][2 * cg + 1][0], ctx[h][2 * cg + 1][1],
                                pg[h][2 * kt][0], pg[h][2 * kt][1],
                                pg[h][2 * kt + 1][0], pg[h][2 * kt + 1][1],
                                vpf[cur][2], vpf[cur][3]);
                }
            }
        }

        // ---- issue cp.async for tile it+2 into buf (it+2)%3 ----
        if (it + 2 < ITERS) {
            const uint32_t NB = sal + (uint32_t)(((it + 2) % 3) * 65536);
            const __half* gsrc = Gbase + (size_t)(it + 2) * MT * CC;
            const __half* vsrc = Vbase + (size_t)(it + 2) * MT * CC;
            #pragma unroll
            for (int idx = tid; idx < 2048; idx += 256) {
                int r = idx >> 4, kc = idx & 15;
                uint32_t off = blk_off(r, kc * 8);
                cp16(NB + off,         gsrc + (size_t)r * CC + kc * 8);
                cp16(NB + 32768 + off, vsrc + (size_t)r * CC + kc * 8);
            }
            CP_COMMIT();
        }
    }
    __syncthreads();   // all PV done; buffers free

    // ---- l partials ----
    #pragma unroll
    for (int h = 0; h < 2; ++h) {
        float2 v0 = __half22float2(*(__half2*)&lacc[h][0]);
        float2 v1 = __half22float2(*(__half2*)&lacc[h][1]);
        float l0 = v0.x + v0.y;
        float l1 = v1.x + v1.y;
        l0 += __shfl_xor_sync(0xffffffffu, l0, 1);
        l0 += __shfl_xor_sync(0xffffffffu, l0, 2);
        l1 += __shfl_xor_sync(0xffffffffu, l1, 1);
        l1 += __shfl_xor_sync(0xffffffffu, l1, 2);
        if ((lane & 3) == 0) {
            int row = qw + 16 * h + (lane >> 2);
            lred[row * 2 + kh]       = l0;
            lred[(row + 8) * 2 + kh] = l1;
        }
    }

    // ---- phase 1: kh=0 stores ctx tile into B0 region ----
    if (kh == 0) {
        #pragma unroll
        for (int h = 0; h < 2; ++h)
            #pragma unroll
            for (int t = 0; t < 16; ++t) {
                int row = qw + 16 * h + (lane >> 2);
                int col = 8 * t + 2 * (lane & 3);
                *(uint32_t*)(smp + SM_B0 + blk_off(row, col))     = ctx[h][t][0];
                *(uint32_t*)(smp + SM_B0 + blk_off(row + 8, col)) = ctx[h][t][1];
            }
    }
    __syncthreads();

    // ---- phase 2: kh=1 adds its ctx; kh=0 warps load Wv tile into B1 ----
    if (kh == 1) {
        #pragma unroll
        for (int h = 0; h < 2; ++h)
            #pragma unroll
            for (int t = 0; t < 16; ++t) {
                int row = qw + 16 * h + (lane >> 2);
                int col = 8 * t + 2 * (lane & 3);
                uint32_t* p0 = (uint32_t*)(smp + SM_B0 + blk_off(row, col));
                uint32_t* p1 = (uint32_t*)(smp + SM_B0 + blk_off(row + 8, col));
                __half2 s0 = __hadd2(*(__half2*)p0, *(__half2*)&ctx[h][t][0]);
                __half2 s1 = __hadd2(*(__half2*)p1, *(__half2*)&ctx[h][t][1]);
                *p0 = *(uint32_t*)&s0;
                *p1 = *(uint32_t*)&s1;
            }
    } else {
        #pragma unroll
        for (int idx = tid; idx < 2048; idx += 128) {   // kh==0: 128 threads
            int r = idx >> 4, kc = idx & 15;
            const float4* s = (const float4*)(Wv + (size_t)r * CC + kc * 8);
            float4 v0 = s[0], v1 = s[1];
            uint4 pk;
            pk.x = pack_f16x2(v0.x, v0.y); pk.y = pack_f16x2(v0.z, v0.w);
            pk.z = pack_f16x2(v1.x, v1.y); pk.w = pack_f16x2(v1.z, v1.w);
            *(uint4*)(smp + SM_B1 + blk_off(r, kc * 8)) = pk;
        }
    }
    __syncthreads();

    // ---- phase 3: all 8 warps: out_rows = warp's 16q slice ----
    const int qw16 = 16 * wid;
    float oac[16][4];
    #pragma unroll
    for (int t = 0; t < 16; ++t)
        #pragma unroll
        for (int e = 0; e < 4; ++e) oac[t][e] = 0.f;

    #pragma unroll
    for (int ks = 0; ks < 8; ++ks) {
        uint32_t a[4];
        ldsm_x4(a, sal + SM_B0 + blk_off(qw16 + (lane & 15), 16 * ks + 8 * (lane >> 4)));
        int ncol = 8 * (lane >> 4);
        #pragma unroll
        for (int g = 0; g < 8; ++g) {
            uint32_t bt[4];
            ldsm_x4_t(bt, sal + SM_B1 + blk_off(16 * ks + (lane & 15), 16 * g + ncol));
            mma_f32acc(oac[2 * g],     a[0], a[1], a[2], a[3], bt[0], bt[1]);
            mma_f32acc(oac[2 * g + 1], a[0], a[1], a[2], a[3], bt[2], bt[3]);
        }
    }

    const float gamma = __ldg(gamma_p);
    const int r  = lane >> 2;
    const int c2 = 2 * (lane & 3);
    const float sc0 = gamma / (lred[(qw16 + r) * 2]     + lred[(qw16 + r) * 2 + 1]);
    const float sc1 = gamma / (lred[(qw16 + r + 8) * 2] + lred[(qw16 + r + 8) * 2 + 1]);
    #pragma unroll
    for (int t = 0; t < 16; ++t) {
        int j = 8 * t + c2;
        float bj0 = bvs[j], bj1 = bvs[j + 1];
        size_t base0 = (size_t)(b * NN + q0 + qw16 + r) * CC + j;
        size_t base1 = base0 + 8 * CC;
        float2 x0 = *(const float2*)(x + base0);
        float2 x1 = *(const float2*)(x + base1);
        float2 o0, o1;
        o0.x = oac[t][0] * sc0 + bj0 + x0.x;
        o0.y = oac[t][1] * sc0 + bj1 + x0.y;
        o1.x = oac[t][2] * sc1 + bj0 + x1.x;
        o1.y = oac[t][3] * sc1 + bj1 + x1.y;
        *(float2*)(out + base0) = o0;
        *(float2*)(out + base1) = o1;
    }
}

// ===================== launch =====================
extern "C" void kernel_launch(void* const* d_in, const int* in_sizes, int n_in,
                              void* d_out, int out_size)
{
    const float* x     = (const float*)d_in[0];
    const float* Wf    = (const float*)d_in[1];
    const float* bf    = (const float*)d_in[2];
    const float* Wg    = (const float*)d_in[3];
    const float* bg    = (const float*)d_in[4];
    const float* Wh    = (const float*)d_in[5];
    const float* bh    = (const float*)d_in[6];
    const float* Wv    = (const float*)d_in[7];
    const float* bv    = (const float*)d_in[8];
    const float* gamma = (const float*)d_in[9];
    float* out = (float*)d_out;

    const int smem_proj = 2 * 32768 + 1024;
    const int smem_attn = SM_ATTN;

    cudaFuncSetAttribute(proj_kernel, cudaFuncAttributeMaxDynamicSharedMemorySize, smem_proj);
    cudaFuncSetAttribute(attn_kernel, cudaFuncAttributeMaxDynamicSharedMemorySize, smem_attn);

    dim3 pgrid(BATCH * NN / 128, 3);
    proj_kernel<<<pgrid, 256, smem_proj>>>(x, Wf, bf, Wg, bg, Wh, bh);

    dim3 grid(NN / QT, BATCH);
    attn_kernel<<<grid, 256, smem_attn>>>(x, Wv, bv, gamma, out);
}

// round 15
// speedup vs baseline: 1.0880x; 1.0155x over previous
#include <cuda_runtime.h>
#include <cuda_fp16.h>
#include <math.h>
#include <stdint.h>

#define BATCH 4
#define NN 4096
#define CC 128
#define QT 128
#define MT 128
#define ITERS (NN / MT)

// f16 scratch, row-major [b*n][c]. Fb is pre-scaled by log2(e).
__device__ __align__(16) __half Fb[BATCH * NN * CC];
__device__ __align__(16) __half Gb[BATCH * NN * CC];
__device__ __align__(16) __half Vb[BATCH * NN * CC];

// ===================== helpers =====================
__device__ __forceinline__ uint32_t smem_u32(const void* p) {
    uint32_t a;
    asm("{ .reg .u64 t; cvta.to.shared.u64 t, %1; cvt.u32.u64 %0, t; }" : "=r"(a) : "l"(p));
    return a;
}
__device__ __forceinline__ uint32_t pack_f16x2(float lo, float hi) {
    uint32_t r;
    asm("cvt.rn.f16x2.f32 %0, %1, %2;" : "=r"(r) : "f"(hi), "f"(lo));
    return r;
}
__device__ __forceinline__ uint32_t ex2_f16x2(uint32_t a) {
    uint32_t r;
    asm("ex2.approx.f16x2 %0, %1;" : "=r"(r) : "r"(a));
    return r;
}
__device__ __forceinline__ uint32_t hadd2u(uint32_t a, uint32_t b) {
    uint32_t r;
    asm("add.f16x2 %0, %1, %2;" : "=r"(r) : "r"(a), "r"(b));
    return r;
}
// blocked SW128 layout for a [128 rows][128 halves] f16 tile (32 KB)
__device__ __forceinline__ uint32_t blk_off(int r, int k) {
    uint32_t byte = ((uint32_t)((r >> 3) + ((k >> 6) << 4)) << 10)
                  + ((uint32_t)(r & 7) << 7) + ((uint32_t)(k & 63) << 1);
    return byte ^ ((byte >> 3) & 0x70);
}
__device__ __forceinline__ void ldsm_x4(uint32_t (&r)[4], uint32_t addr) {
    asm volatile("ldmatrix.sync.aligned.m8n8.x4.shared.b16 {%0,%1,%2,%3}, [%4];"
                 : "=r"(r[0]), "=r"(r[1]), "=r"(r[2]), "=r"(r[3]) : "r"(addr));
}
__device__ __forceinline__ void ldsm_x4_t(uint32_t (&r)[4], uint32_t addr) {
    asm volatile("ldmatrix.sync.aligned.m8n8.x4.trans.shared.b16 {%0,%1,%2,%3}, [%4];"
                 : "=r"(r[0]), "=r"(r[1]), "=r"(r[2]), "=r"(r[3]) : "r"(addr));
}
__device__ __forceinline__ void mma_f32acc(float (&d)[4], uint32_t a0, uint32_t a1,
                                           uint32_t a2, uint32_t a3,
                                           uint32_t b0, uint32_t b1) {
    asm volatile("mma.sync.aligned.m16n8k16.row.col.f32.f16.f16.f32 "
                 "{%0,%1,%2,%3},{%4,%5,%6,%7},{%8,%9},{%0,%1,%2,%3};"
                 : "+f"(d[0]), "+f"(d[1]), "+f"(d[2]), "+f"(d[3])
                 : "r"(a0), "r"(a1), "r"(a2), "r"(a3), "r"(b0), "r"(b1));
}
__device__ __forceinline__ void mma_f16acc2(uint32_t& d0, uint32_t& d1,
                                            uint32_t a0, uint32_t a1,
                                            uint32_t a2, uint32_t a3,
                                            uint32_t b0, uint32_t b1) {
    asm volatile("mma.sync.aligned.m16n8k16.row.col.f16.f16.f16.f16 "
                 "{%0,%1},{%2,%3,%4,%5},{%6,%7},{%0,%1};"
                 : "+r"(d0), "+r"(d1)
                 : "r"(a0), "r"(a1), "r"(a2), "r"(a3), "r"(b0), "r"(b1));
}
__device__ __forceinline__ void cp16(uint32_t d, const void* s) {
    asm volatile("cp.async.cg.shared.global [%0], [%1], 16;" :: "r"(d), "l"(s) : "memory");
}
#define CP_COMMIT() asm volatile("cp.async.commit_group;" ::: "memory")
#define CP_WAIT0()  asm volatile("cp.async.wait_group 0;" ::: "memory")
#define CP_WAIT1()  asm volatile("cp.async.wait_group 1;" ::: "memory")

#define LOG2E 1.4426950408889634f

// ===================== Kernel A: projections, one weight per CTA =====================
__global__ __launch_bounds__(256, 1)
void proj_kernel(const float* __restrict__ x,
                 const float* __restrict__ Wf, const float* __restrict__ bf,
                 const float* __restrict__ Wg, const float* __restrict__ bg,
                 const float* __restrict__ Wh, const float* __restrict__ bh)
{
    extern __shared__ char smraw[];
    const uint32_t sbase = smem_u32(smraw);
    const uint32_t sal   = (sbase + 1023u) & ~1023u;
    char* smp = smraw + (sal - sbase);
    const uint32_t XT = sal, WT = sal + 32768;

    const int tid  = threadIdx.x;
    const int lane = tid & 31;
    const int wid  = tid >> 5;
    const int wm   = wid & 3;
    const int wn   = wid >> 2;
    const int row0 = blockIdx.x * 128;
    const int w    = blockIdx.y;

    const float* W  = (w == 0) ? Wf : (w == 1 ? Wg : Wh);
    const float* bs = (w == 0) ? bf : (w == 1 ? bg : bh);

    #pragma unroll
    for (int idx = tid; idx < 2048; idx += 256) {
        int r = idx >> 4, kc = idx & 15;
        const float4* s0 = (const float4*)(x + (size_t)(row0 + r) * CC + kc * 8);
        const float4* s1 = (const float4*)(W + (size_t)r * CC + kc * 8);
        float4 v0 = s0[0], v1 = s0[1];
        uint4 pk;
        pk.x = pack_f16x2(v0.x, v0.y); pk.y = pack_f16x2(v0.z, v0.w);
        pk.z = pack_f16x2(v1.x, v1.y); pk.w = pack_f16x2(v1.z, v1.w);
        *(uint4*)(smp + (XT - sal) + blk_off(r, kc * 8)) = pk;
        v0 = s1[0]; v1 = s1[1];
        pk.x = pack_f16x2(v0.x, v0.y); pk.y = pack_f16x2(v0.z, v0.w);
        pk.z = pack_f16x2(v1.x, v1.y); pk.w = pack_f16x2(v1.z, v1.w);
        *(uint4*)(smp + (WT - sal) + blk_off(r, kc * 8)) = pk;
    }
    float bc[16];
    #pragma unroll
    for (int t = 0; t < 16; ++t)
        bc[t] = bs[64 * wn + 8 * (t >> 1) + 2 * (lane & 3) + (t & 1)];
    __syncthreads();

    float acc[2][8][4];
    #pragma unroll
    for (int i = 0; i < 2; ++i)
        #pragma unroll
        for (int j = 0; j < 8; ++j)
            #pragma unroll
            for (int e = 0; e < 4; ++e) acc[i][j][e] = 0.f;

    #pragma unroll
    for (int ks = 0; ks < 8; ++ks) {
        uint32_t a0[4], a1[4];
        int kcol = 16 * ks + 8 * (lane >> 4);
        ldsm_x4(a0, XT + blk_off(32 * wm + (lane & 15), kcol));
        ldsm_x4(a1, XT + blk_off(32 * wm + 16 + (lane & 15), kcol));
        #pragma unroll
        for (int g = 0; g < 4; ++g) {
            uint32_t bt[4];
            ldsm_x4_t(bt, WT + blk_off(16 * ks + (lane & 15),
                                       64 * wn + 16 * g + 8 * (lane >> 4)));
            mma_f32acc(acc[0][2 * g],     a0[0], a0[1], a0[2], a0[3], bt[0], bt[1]);
            mma_f32acc(acc[0][2 * g + 1], a0[0], a0[1], a0[2], a0[3], bt[2], bt[3]);
            mma_f32acc(acc[1][2 * g],     a1[0], a1[1], a1[2], a1[3], bt[0], bt[1]);
            mma_f32acc(acc[1][2 * g + 1], a1[0], a1[1], a1[2], a1[3], bt[2], bt[3]);
        }
    }

    const float osc = (w == 0) ? LOG2E : 1.0f;   // fold log2e into F
    uint32_t* dst = (uint32_t*)(w == 0 ? Fb : (w == 1 ? Gb : Vb));
    #pragma unroll
    for (int mi = 0; mi < 2; ++mi)
        #pragma unroll
        for (int nj = 0; nj < 8; ++nj) {
            int row  = row0 + 32 * wm + 16 * mi + (lane >> 2);
            int colp = 32 * wn + 4 * nj + (lane & 3);
            float b0 = bc[2 * nj], b1 = bc[2 * nj + 1];
            dst[(size_t)row * 64 + colp] =
                pack_f16x2((acc[mi][nj][0] + b0) * osc, (acc[mi][nj][1] + b1) * osc);
            dst[(size_t)(row + 8) * 64 + colp] =
                pack_f16x2((acc[mi][nj][2] + b0) * osc, (acc[mi][nj][3] + b1) * osc);
        }
}

// ===================== Kernel B: low-register flash attention =====================
// grid (32,4) x 256 thr. 8 warps = 4 qg x 2 kh; warp owns q[32qg,+32) x keys[64kh,+64).
// F stays resident in smem; A-fragments re-read per iteration (regs for scheduling).
// smem: F@0 (32K, persistent), B0@32K (G+V 64K), B1@98304 (64K),
//       bvs@163840 (512B), lred@+512 (1KB). Epilogue: ctx->F, Wv->B0.
#define SM_F    0
#define SM_GV   32768
#define SM_MISC 163840
#define SM_ATTN (163840 + 1536 + 1024)

__global__ __launch_bounds__(256, 1)
void attn_kernel(const float* __restrict__ x,
                 const float* __restrict__ Wv,
                 const float* __restrict__ bv,
                 const float* __restrict__ gamma_p,
                 float* __restrict__ out)
{
    extern __shared__ char smraw[];
    const uint32_t sbase = smem_u32(smraw);
    const uint32_t sal   = (sbase + 1023u) & ~1023u;
    char* smp = smraw + (sal - sbase);

    const int tid  = threadIdx.x;
    const int lane = tid & 31;
    const int wid  = tid >> 5;
    const int qg   = wid & 3;          // 32-q-row group
    const int kh   = wid >> 2;         // 64-key half
    const int qw   = 32 * qg;
    const int b    = blockIdx.y;
    const int q0   = blockIdx.x * QT;

    float* bvs  = (float*)(smp + SM_MISC);
    float* lred = (float*)(smp + SM_MISC + 512);
    if (tid < 128) bvs[tid] = bv[tid];

    const __half* Gbase = Gb + (size_t)b * NN * CC;
    const __half* Vbase = Vb + (size_t)b * NN * CC;

    // stage F tile (pre-scaled by log2e) — persistent through the loop
    #pragma unroll
    for (int idx = tid; idx < 2048; idx += 256) {
        int r = idx >> 4, kc = idx & 15;
        uint4 v = *(const uint4*)(Fb + (size_t)(b * NN + q0 + r) * CC + kc * 8);
        *(uint4*)(smp + SM_F + blk_off(r, kc * 8)) = v;
    }

    // prefetch tile 0 into buffer 0
    #pragma unroll
    for (int idx = tid; idx < 2048; idx += 256) {
        int r = idx >> 4, kc = idx & 15;
        uint32_t off = blk_off(r, kc * 8);
        cp16(sal + SM_GV + off,         Gbase + (size_t)r * CC + kc * 8);
        cp16(sal + SM_GV + 32768 + off, Vbase + (size_t)r * CC + kc * 8);
    }
    CP_COMMIT();

    uint32_t ctx[2][16][2];            // f16 accum: 32q x 128c
    #pragma unroll
    for (int h = 0; h < 2; ++h)
        #pragma unroll
        for (int t = 0; t < 16; ++t) { ctx[h][t][0] = 0u; ctx[h][t][1] = 0u; }
    uint32_t lacc[2][2] = {{0u, 0u}, {0u, 0u}};

    int buf = 0;
    for (int it = 0; it < ITERS; ++it) {
        __syncthreads();               // all warps done with buf^1 (incl. F at it=0)
        if (it + 1 < ITERS) {
            int nb = buf ^ 1;
            const __half* gsrc = Gbase + (size_t)(it + 1) * MT * CC;
            const __half* vsrc = Vbase + (size_t)(it + 1) * MT * CC;
            #pragma unroll
            for (int idx = tid; idx < 2048; idx += 256) {
                int r = idx >> 4, kc = idx & 15;
                uint32_t off = blk_off(r, kc * 8);
                cp16(sal + SM_GV + nb * 65536 + off,         gsrc + (size_t)r * CC + kc * 8);
                cp16(sal + SM_GV + nb * 65536 + 32768 + off, vsrc + (size_t)r * CC + kc * 8);
            }
            CP_COMMIT();
            CP_WAIT1();
        } else {
            CP_WAIT0();
        }
        __syncthreads();               // tile `buf` visible

        const uint32_t GT = sal + SM_GV + buf * 65536;
        const uint32_t VT = GT + 32768;

        // ---- S = F @ G^T (warp's 64-key half), f16 accum; aF re-read per ks ----
        uint32_t pg[2][8][2];
        #pragma unroll
        for (int h = 0; h < 2; ++h)
            #pragma unroll
            for (int j = 0; j < 8; ++j) { pg[h][j][0] = 0u; pg[h][j][1] = 0u; }

        #pragma unroll
        for (int ks = 0; ks < 8; ++ks) {
            const int kcol = 16 * ks + 8 * (lane >> 4);
            uint32_t a0[4], a1[4];
            ldsm_x4(a0, sal + SM_F + blk_off(qw + (lane & 15), kcol));
            ldsm_x4(a1, sal + SM_F + blk_off(qw + 16 + (lane & 15), kcol));
            #pragma unroll
            for (int g = 0; g < 4; ++g) {
                uint32_t bt[4];
                ldsm_x4(bt, GT + blk_off(64 * kh + 16 * g + (lane & 15), kcol));
                mma_f16acc2(pg[0][2 * g][0],     pg[0][2 * g][1],
                            a0[0], a0[1], a0[2], a0[3], bt[0], bt[2]);
                mma_f16acc2(pg[0][2 * g + 1][0], pg[0][2 * g + 1][1],
                            a0[0], a0[1], a0[2], a0[3], bt[1], bt[3]);
                mma_f16acc2(pg[1][2 * g][0],     pg[1][2 * g][1],
                            a1[0], a1[1], a1[2], a1[3], bt[0], bt[2]);
                mma_f16acc2(pg[1][2 * g + 1][0], pg[1][2 * g + 1][1],
                            a1[0], a1[1], a1[2], a1[3], bt[1], bt[3]);
            }
        }

        // ---- P = 2^S in place; row sums on ALU pipe ----
        #pragma unroll
        for (int h = 0; h < 2; ++h)
            #pragma unroll
            for (int j = 0; j < 8; ++j) {
                pg[h][j][0] = ex2_f16x2(pg[h][j][0]);
                pg[h][j][1] = ex2_f16x2(pg[h][j][1]);
                lacc[h][0] = hadd2u(lacc[h][0], pg[h][j][0]);
                lacc[h][1] = hadd2u(lacc[h][1], pg[h][j][1]);
            }

        // ---- ctx += P @ V (warp's 64 key rows) ----
        #pragma unroll
        for (int kt = 0; kt < 4; ++kt) {
            const int vrow = 64 * kh + 16 * kt + (lane & 15);
            const int ncol = 8 * (lane >> 4);
            #pragma unroll
            for (int cg = 0; cg < 8; ++cg) {
                uint32_t bt[4];
                ldsm_x4_t(bt, VT + blk_off(vrow, 16 * cg + ncol));
                #pragma unroll
                for (int h = 0; h < 2; ++h) {
                    mma_f16acc2(ctx[h][2 * cg][0],     ctx[h][2 * cg][1],
                                pg[h][2 * kt][0], pg[h][2 * kt][1],
                                pg[h][2 * kt + 1][0], pg[h][2 * kt + 1][1], bt[0], bt[1]);
                    mma_f16acc2(ctx[h][2 * cg + 1][0], ctx[h][2 * cg + 1][1],
                                pg[h][2 * kt][0], pg[h][2 * kt][1],
                                pg[h][2 * kt + 1][0], pg[h][2 * kt + 1][1], bt[2], bt[3]);
                }
            }
        }
        buf ^= 1;
    }
    __syncthreads();   // all warps done with F + GV buffers

    // ---- l partials ----
    #pragma unroll
    for (int h = 0; h < 2; ++h) {
        float2 v0 = __half22float2(*(__half2*)&lacc[h][0]);
        float2 v1 = __half22float2(*(__half2*)&lacc[h][1]);
        float l0 = v0.x + v0.y;
        float l1 = v1.x + v1.y;
        l0 += __shfl_xor_sync(0xffffffffu, l0, 1);
        l0 += __shfl_xor_sync(0xffffffffu, l0, 2);
        l1 += __shfl_xor_sync(0xffffffffu, l1, 1);
        l1 += __shfl_xor_sync(0xffffffffu, l1, 2);
        if ((lane & 3) == 0) {
            int row = qw + 16 * h + (lane >> 2);
            lred[row * 2 + kh]       = l0;
            lred[(row + 8) * 2 + kh] = l1;
        }
    }

    // ---- phase 1: kh=0 stores ctx tile into F region ----
    if (kh == 0) {
        #pragma unroll
        for (int h = 0; h < 2; ++h)
            #pragma unroll
            for (int t = 0; t < 16; ++t) {
                int row = qw + 16 * h + (lane >> 2);
                int col = 8 * t + 2 * (lane & 3);
                *(uint32_t*)(smp + SM_F + blk_off(row, col))     = ctx[h][t][0];
                *(uint32_t*)(smp + SM_F + blk_off(row + 8, col)) = ctx[h][t][1];
            }
    }
    __syncthreads();

    // ---- phase 2: kh=1 adds its ctx; kh=0 warps load Wv tile into B0 ----
    if (kh == 1) {
        #pragma unroll
        for (int h = 0; h < 2; ++h)
            #pragma unroll
            for (int t = 0; t < 16; ++t) {
                int row = qw + 16 * h + (lane >> 2);
                int col = 8 * t + 2 * (lane & 3);
                uint32_t* p0 = (uint32_t*)(smp + SM_F + blk_off(row, col));
                uint32_t* p1 = (uint32_t*)(smp + SM_F + blk_off(row + 8, col));
                __half2 s0 = __hadd2(*(__half2*)p0, *(__half2*)&ctx[h][t][0]);
                __half2 s1 = __hadd2(*(__half2*)p1, *(__half2*)&ctx[h][t][1]);
                *p0 = *(uint32_t*)&s0;
                *p1 = *(uint32_t*)&s1;
            }
    } else {
        #pragma unroll
        for (int idx = tid; idx < 2048; idx += 128) {   // kh==0: 128 threads
            int r = idx >> 4, kc = idx & 15;
            const float4* s = (const float4*)(Wv + (size_t)r * CC + kc * 8);
            float4 v0 = s[0], v1 = s[1];
            uint4 pk;
            pk.x = pack_f16x2(v0.x, v0.y); pk.y = pack_f16x2(v0.z, v0.w);
            pk.z = pack_f16x2(v1.x, v1.y); pk.w = pack_f16x2(v1.z, v1.w);
            *(uint4*)(smp + SM_GV + blk_off(r, kc * 8)) = pk;
        }
    }
    __syncthreads();

    // ---- phase 3: all 8 warps: out_rows = warp's 16q slice ----
    const int qw16 = 16 * wid;
    float oac[16][4];
    #pragma unroll
    for (int t = 0; t < 16; ++t)
        #pragma unroll
        for (int e = 0; e < 4; ++e) oac[t][e] = 0.f;

    #pragma unroll
    for (int ks = 0; ks < 8; ++ks) {
        uint32_t a[4];
        ldsm_x4(a, sal + SM_F + blk_off(qw16 + (lane & 15), 16 * ks + 8 * (lane >> 4)));
        int ncol = 8 * (lane >> 4);
        #pragma unroll
        for (int g = 0; g < 8; ++g) {
            uint32_t bt[4];
            ldsm_x4_t(bt, sal + SM_GV + blk_off(16 * ks + (lane & 15), 16 * g + ncol));
            mma_f32acc(oac[2 * g],     a[0], a[1], a[2], a[3], bt[0], bt[1]);
            mma_f32acc(oac[2 * g + 1], a[0], a[1], a[2], a[3], bt[2], bt[3]);
        }
    }

    const float gamma = __ldg(gamma_p);
    const int r  = lane >> 2;
    const int c2 = 2 * (lane & 3);
    const float sc0 = gamma / (lred[(qw16 + r) * 2]     + lred[(qw16 + r) * 2 + 1]);
    const float sc1 = gamma / (lred[(qw16 + r + 8) * 2] + lred[(qw16 + r + 8) * 2 + 1]);
    #pragma unroll
    for (int t = 0; t < 16; ++t) {
        int j = 8 * t + c2;
        float bj0 = bvs[j], bj1 = bvs[j + 1];
        size_t base0 = (size_t)(b * NN + q0 + qw16 + r) * CC + j;
        size_t base1 = base0 + 8 * CC;
        float2 x0 = *(const float2*)(x + base0);
        float2 x1 = *(const float2*)(x + base1);
        float2 o0, o1;
        o0.x = oac[t][0] * sc0 + bj0 + x0.x;
        o0.y = oac[t][1] * sc0 + bj1 + x0.y;
        o1.x = oac[t][2] * sc1 + bj0 + x1.x;
        o1.y = oac[t][3] * sc1 + bj1 + x1.y;
        *(float2*)(out + base0) = o0;
        *(float2*)(out + base1) = o1;
    }
}

// ===================== launch =====================
extern "C" void kernel_launch(void* const* d_in, const int* in_sizes, int n_in,
                              void* d_out, int out_size)
{
    const float* x     = (const float*)d_in[0];
    const float* Wf    = (const float*)d_in[1];
    const float* bf    = (const float*)d_in[2];
    const float* Wg    = (const float*)d_in[3];
    const float* bg    = (const float*)d_in[4];
    const float* Wh    = (const float*)d_in[5];
    const float* bh    = (const float*)d_in[6];
    const float* Wv    = (const float*)d_in[7];
    const float* bv    = (const float*)d_in[8];
    const float* gamma = (const float*)d_in[9];
    float* out = (float*)d_out;

    const int smem_proj = 2 * 32768 + 1024;
    const int smem_attn = SM_ATTN;

    cudaFuncSetAttribute(proj_kernel, cudaFuncAttributeMaxDynamicSharedMemorySize, smem_proj);
    cudaFuncSetAttribute(attn_kernel, cudaFuncAttributeMaxDynamicSharedMemorySize, smem_attn);

    dim3 pgrid(BATCH * NN / 128, 3);
    proj_kernel<<<pgrid, 256, smem_proj>>>(x, Wf, bf, Wg, bg, Wh, bh);

    dim3 grid(NN / QT, BATCH);
    attn_kernel<<<grid, 256, smem_attn>>>(x, Wv, bv, gamma, out);
}